// round 2
// baseline (speedup 1.0000x reference)
#include <cuda_runtime.h>
#include <math.h>

#define T_SEQ 4096
#define C_EMB 768
#define NH    12
#define HD    64

// Scratch (allocation-guard-safe __device__ globals)
__device__ __align__(128) float g_q[(size_t)NH * T_SEQ * HD];
__device__ __align__(128) float g_k[(size_t)NH * T_SEQ * HD];
__device__ __align__(128) float g_v[(size_t)NH * T_SEQ * HD];
__device__ __align__(128) float g_att[(size_t)T_SEQ * C_EMB];

// ---------------------------------------------------------------------------
// GEMM: C[t,o] = sum_c X[t,c] * W[o,c]   (X:[T,768] row-major, W:[768,768])
// mode 0: X := g_att, write out[T,768] (final projection)
// mode 1/2/3: X := Xin, write head-major g_q/g_k/g_v  [h][t][d]
// 64x64 tile, 256 threads, 4x4 per thread, TK=16, pad-17 smem rows.
// ---------------------------------------------------------------------------
__global__ __launch_bounds__(256) void gemm_xwT(const float* __restrict__ Xin,
                                                const float* __restrict__ W,
                                                float* __restrict__ out,
                                                int mode) {
    __shared__ float As[64][17];
    __shared__ float Bs[64][17];
    const float* X = (mode == 0) ? g_att : Xin;
    const int tid = threadIdx.x;
    const int tx = tid & 15, ty = tid >> 4;
    const int row0 = blockIdx.x * 64;
    const int col0 = blockIdx.y * 64;
    const int lr = tid >> 2;          // 0..63
    const int lc = (tid & 3) << 2;    // 0,4,8,12
    float acc[4][4] = {};

    for (int k0 = 0; k0 < C_EMB; k0 += 16) {
        float4 a = *(const float4*)(X + (size_t)(row0 + lr) * C_EMB + k0 + lc);
        float4 b = *(const float4*)(W + (size_t)(col0 + lr) * C_EMB + k0 + lc);
        As[lr][lc + 0] = a.x; As[lr][lc + 1] = a.y;
        As[lr][lc + 2] = a.z; As[lr][lc + 3] = a.w;
        Bs[lr][lc + 0] = b.x; Bs[lr][lc + 1] = b.y;
        Bs[lr][lc + 2] = b.z; Bs[lr][lc + 3] = b.w;
        __syncthreads();
#pragma unroll
        for (int kk = 0; kk < 16; kk++) {
            float av[4], bv[4];
#pragma unroll
            for (int i = 0; i < 4; i++) av[i] = As[ty * 4 + i][kk];
#pragma unroll
            for (int j = 0; j < 4; j++) bv[j] = Bs[tx * 4 + j][kk];
#pragma unroll
            for (int i = 0; i < 4; i++)
#pragma unroll
                for (int j = 0; j < 4; j++)
                    acc[i][j] = fmaf(av[i], bv[j], acc[i][j]);
        }
        __syncthreads();
    }

    if (mode == 0) {
#pragma unroll
        for (int i = 0; i < 4; i++)
#pragma unroll
            for (int j = 0; j < 4; j++)
                out[(size_t)(row0 + ty * 4 + i) * C_EMB + col0 + tx * 4 + j] = acc[i][j];
    } else {
        float* dst = (mode == 1) ? g_q : (mode == 2) ? g_k : g_v;
        const int h = blockIdx.y;   // col tile == head (HD == 64 == tile width)
#pragma unroll
        for (int i = 0; i < 4; i++)
#pragma unroll
            for (int j = 0; j < 4; j++)
                dst[((size_t)h * T_SEQ + row0 + ty * 4 + i) * HD + tx * 4 + j] = acc[i][j];
    }
}

// ---------------------------------------------------------------------------
// Flash attention, fp32, causal.  BLOCK_M = BLOCK_N = 64, D = 64.
// 256 threads: thread (tx,ty) in 16x16 grid owns a 4x4 micro-tile of S/O.
// smem: Qs[64][64] | Kt[64][65] (K transposed) | Ps[64][65] | Vs[64][64]
// ---------------------------------------------------------------------------
__global__ __launch_bounds__(256) void attn_kernel() {
    extern __shared__ float sm[];
    float* Qs = sm;                         // 4096 floats
    float* Kt = sm + 4096;                  // 64*65 = 4160
    float* Ps = sm + 4096 + 4160;           // 4160
    float* Vs = sm + 4096 + 4160 + 4160;    // 4096

    const int tid = threadIdx.x;
    const int tx = tid & 15, ty = tid >> 4;
    const int it = blockIdx.x;              // query tile
    const int h  = blockIdx.y;
    const int q0 = it * 64;

    const float* Qg = g_q + (size_t)h * T_SEQ * HD;
    const float* Kg = g_k + (size_t)h * T_SEQ * HD;
    const float* Vg = g_v + (size_t)h * T_SEQ * HD;

    // Load Q tile (coalesced float4)
#pragma unroll
    for (int rep = 0; rep < 4; rep++) {
        int row = (tid >> 4) + rep * 16;
        int d   = (tid & 15) * 4;
        *(float4*)(Qs + row * 64 + d) =
            *(const float4*)(Qg + (size_t)(q0 + row) * HD + d);
    }

    float m[4], l[4], o[4][4];
#pragma unroll
    for (int i = 0; i < 4; i++) {
        m[i] = -INFINITY; l[i] = 0.f;
#pragma unroll
        for (int j = 0; j < 4; j++) o[i][j] = 0.f;
    }
    __syncthreads();

    for (int jt = 0; jt <= it; jt++) {
        const int k0 = jt * 64;
        // Load K (transposed into smem) and V
#pragma unroll
        for (int rep = 0; rep < 4; rep++) {
            int row = (tid >> 4) + rep * 16;
            int d   = (tid & 15) * 4;
            float4 kv = *(const float4*)(Kg + (size_t)(k0 + row) * HD + d);
            Kt[(d + 0) * 65 + row] = kv.x;
            Kt[(d + 1) * 65 + row] = kv.y;
            Kt[(d + 2) * 65 + row] = kv.z;
            Kt[(d + 3) * 65 + row] = kv.w;
            *(float4*)(Vs + row * 64 + d) =
                *(const float4*)(Vg + (size_t)(k0 + row) * HD + d);
        }
        __syncthreads();

        // S = Q @ K^T (64x64 tile)
        float s[4][4] = {};
#pragma unroll 16
        for (int kk = 0; kk < 64; kk++) {
            float qv[4], kv[4];
#pragma unroll
            for (int i = 0; i < 4; i++) qv[i] = Qs[(ty * 4 + i) * 64 + kk];
#pragma unroll
            for (int j = 0; j < 4; j++) kv[j] = Kt[kk * 65 + tx * 4 + j];
#pragma unroll
            for (int i = 0; i < 4; i++)
#pragma unroll
                for (int j = 0; j < 4; j++)
                    s[i][j] = fmaf(qv[i], kv[j], s[i][j]);
        }

        const float scale = 0.125f;   // 1/sqrt(64)
#pragma unroll
        for (int i = 0; i < 4; i++)
#pragma unroll
            for (int j = 0; j < 4; j++) s[i][j] *= scale;
        if (jt == it) {
#pragma unroll
            for (int i = 0; i < 4; i++)
#pragma unroll
                for (int j = 0; j < 4; j++)
                    if (k0 + tx * 4 + j > q0 + ty * 4 + i) s[i][j] = -INFINITY;
        }

        // Online softmax (row groups of 16 lanes: same ty, tx 0..15)
#pragma unroll
        for (int i = 0; i < 4; i++) {
            float mt = fmaxf(fmaxf(s[i][0], s[i][1]), fmaxf(s[i][2], s[i][3]));
            mt = fmaxf(mt, __shfl_xor_sync(0xffffffffu, mt, 1));
            mt = fmaxf(mt, __shfl_xor_sync(0xffffffffu, mt, 2));
            mt = fmaxf(mt, __shfl_xor_sync(0xffffffffu, mt, 4));
            mt = fmaxf(mt, __shfl_xor_sync(0xffffffffu, mt, 8));
            float mn = fmaxf(m[i], mt);
            float corr = __expf(m[i] - mn);
            m[i] = mn;
            float rs = 0.f;
#pragma unroll
            for (int j = 0; j < 4; j++) {
                float p = __expf(s[i][j] - mn);
                Ps[(ty * 4 + i) * 65 + tx * 4 + j] = p;
                rs += p;
            }
            rs += __shfl_xor_sync(0xffffffffu, rs, 1);
            rs += __shfl_xor_sync(0xffffffffu, rs, 2);
            rs += __shfl_xor_sync(0xffffffffu, rs, 4);
            rs += __shfl_xor_sync(0xffffffffu, rs, 8);
            l[i] = l[i] * corr + rs;
#pragma unroll
            for (int j = 0; j < 4; j++) o[i][j] *= corr;
        }
        __syncthreads();   // Ps visible to all

        // O += P @ V
#pragma unroll 8
        for (int ss = 0; ss < 64; ss++) {
            float pv[4];
#pragma unroll
            for (int i = 0; i < 4; i++) pv[i] = Ps[(ty * 4 + i) * 65 + ss];
            float4 vv = *(const float4*)(Vs + ss * 64 + tx * 4);
#pragma unroll
            for (int i = 0; i < 4; i++) {
                o[i][0] = fmaf(pv[i], vv.x, o[i][0]);
                o[i][1] = fmaf(pv[i], vv.y, o[i][1]);
                o[i][2] = fmaf(pv[i], vv.z, o[i][2]);
                o[i][3] = fmaf(pv[i], vv.w, o[i][3]);
            }
        }
        __syncthreads();   // done with Ps/Vs before next tile load
    }

    // Normalize and write to att buffer [T, 768] (head columns interleaved)
#pragma unroll
    for (int i = 0; i < 4; i++) {
        float inv = 1.f / l[i];
#pragma unroll
        for (int j = 0; j < 4; j++)
            g_att[(size_t)(q0 + ty * 4 + i) * C_EMB + h * HD + tx * 4 + j] =
                o[i][j] * inv;
    }
}

// ---------------------------------------------------------------------------
extern "C" void kernel_launch(void* const* d_in, const int* in_sizes, int n_in,
                              void* d_out, int out_size) {
    (void)in_sizes; (void)n_in; (void)out_size;
    const float* x  = (const float*)d_in[0];
    const float* wq = (const float*)d_in[1];
    const float* wk = (const float*)d_in[2];
    const float* wv = (const float*)d_in[3];
    const float* wo = (const float*)d_in[4];
    float* out = (float*)d_out;

    const int attn_smem = (4096 + 4160 + 4160 + 4096) * 4;  // 66048 B
    cudaFuncSetAttribute(attn_kernel,
                         cudaFuncAttributeMaxDynamicSharedMemorySize, attn_smem);

    dim3 gemm_grid(T_SEQ / 64, C_EMB / 64);   // 64 x 12
    gemm_xwT<<<gemm_grid, 256>>>(x, wq, nullptr, 1);
    gemm_xwT<<<gemm_grid, 256>>>(x, wk, nullptr, 2);
    gemm_xwT<<<gemm_grid, 256>>>(x, wv, nullptr, 3);

    dim3 attn_grid(T_SEQ / 64, NH);           // 64 x 12
    attn_kernel<<<attn_grid, 256, attn_smem>>>();

    gemm_xwT<<<gemm_grid, 256>>>(nullptr, wo, out, 0);
}